// round 2
// baseline (speedup 1.0000x reference)
#include <cuda_runtime.h>
#include <cuda_bf16.h>
#include <math.h>

// JastrowUpdate: j = occ_so @ W + b  (B x 256), view as (B,16,16),
// slogdet(I + j) -> sign (B), logabs (B). Output assumed [sign | logabs].

#define RANKD 16
#define NE    128
#define RR    256          // RANK*RANK
#define THREADS 256
#define WARPS_PER_CTA 8
#define ROWS_PER_WARP 4
#define ROWS_PER_CTA 128   // 8 warps * 4 rows * 4 iters
#define JPAD 264           // 256 + 8 padding

// shared layout (floats): Wsm[128*256] | bsm[256] | jbuf[8][4][264]
#define WSM_SIZE (NE * RR)
#define BSM_OFF  WSM_SIZE
#define JBUF_OFF (WSM_SIZE + RR)
#define JBUF_PER_WARP (ROWS_PER_WARP * JPAD)
#define SMEM_FLOATS (JBUF_OFF + WARPS_PER_CTA * JBUF_PER_WARP)

__device__ __forceinline__ void lu16x2(float r[16], int lane,
                                       float& sign_out, float& logabs_out) {
    const unsigned FULL = 0xFFFFFFFFu;
    const int half = lane >> 4;       // 0: matrix A, 1: matrix B
    const int l16  = lane & 15;
    const int base = half << 4;

    int   cur_pos = l16;              // simulated row position (for pivot parity)
    float sign    = 1.0f;
    float logabs  = 0.0f;

#pragma unroll
    for (int k = 0; k < 16; k++) {
        // candidate: |a[i][k]| for rows not yet used as pivot
        float cand = (cur_pos >= k) ? fabsf(r[k]) : -1.0f;
        int   idx  = l16;
        // argmax over the 16-lane half (xor distances 1,2,4,8 stay in-half)
#pragma unroll
        for (int d = 1; d < 16; d <<= 1) {
            float v2 = __shfl_xor_sync(FULL, cand, d);
            int   i2 = __shfl_xor_sync(FULL, idx,  d);
            if (v2 > cand || (v2 == cand && i2 < idx)) { cand = v2; idx = i2; }
        }
        const int psrc = base + idx;                       // pivot lane (global)
        const float piv  = __shfl_sync(FULL, r[k],    psrc);
        const int  pos_p = __shfl_sync(FULL, cur_pos, psrc);

        // permutation parity: a swap happens iff pivot row isn't already at k
        if (pos_p != k) sign = -sign;
        if (cur_pos == k) cur_pos = pos_p;                 // lane sitting at k takes pivot's slot
        if (l16 == idx)  cur_pos = k;                      // pivot lane now at position k

        sign  *= (piv > 0.0f) ? 1.0f : ((piv < 0.0f) ? -1.0f : 0.0f);
        logabs += logf(fabsf(piv));

        const float pinv = 1.0f / piv;
        const float m    = r[k] * pinv;
        const bool  act  = (cur_pos > k);                  // rows still to eliminate
#pragma unroll
        for (int j = k + 1; j < 16; j++) {
            float prj = __shfl_sync(FULL, r[j], psrc);
            if (act) r[j] = fmaf(-m, prj, r[j]);
        }
    }
    sign_out = sign; logabs_out = logabs;
}

__global__ __launch_bounds__(THREADS)
void jastrow_kernel(const float* __restrict__ occ,
                    const float* __restrict__ W,
                    const float* __restrict__ b,
                    float* __restrict__ out_sign,
                    float* __restrict__ out_log,
                    int nrows) {
    extern __shared__ float smem[];
    float* Wsm  = smem;
    float* bsm  = smem + BSM_OFF;
    float* jbuf = smem + JBUF_OFF;

    const int tid  = threadIdx.x;
    const int lane = tid & 31;
    const int warp = tid >> 5;
    const unsigned FULL = 0xFFFFFFFFu;

    // stage W (128KB) + b into shared memory, coalesced float4
    {
        const float4* Wv = (const float4*)W;
        float4* Wsv = (float4*)Wsm;
#pragma unroll
        for (int i = 0; i < (WSM_SIZE / 4) / THREADS; i++)
            Wsv[tid + i * THREADS] = Wv[tid + i * THREADS];
        if (tid < RR) bsm[tid] = b[tid];
    }
    __syncthreads();

    const int cta_base = blockIdx.x * ROWS_PER_CTA;
    float* myj = jbuf + warp * JBUF_PER_WARP;

    for (int t = 0; t < ROWS_PER_CTA / (WARPS_PER_CTA * ROWS_PER_WARP); t++) {
        const int rowbase = cta_base + t * (WARPS_PER_CTA * ROWS_PER_WARP)
                          + warp * ROWS_PER_WARP;
        if (rowbase >= nrows) continue;

        // ---- load occ rows: o[r][kk] holds occ[row_r][kk*32 + lane] ----
        float o[ROWS_PER_WARP][4];
#pragma unroll
        for (int r = 0; r < ROWS_PER_WARP; r++) {
            const float* p = occ + (size_t)(rowbase + r) * NE;
#pragma unroll
            for (int kk = 0; kk < 4; kk++)
                o[r][kk] = p[kk * 32 + lane];
        }

        // ---- GEMM: acc[r][0..7] = row_r dot W[:, lane*8 .. lane*8+7] ----
        float acc[ROWS_PER_WARP][8];
#pragma unroll
        for (int r = 0; r < ROWS_PER_WARP; r++)
#pragma unroll
            for (int c = 0; c < 8; c++) acc[r][c] = 0.0f;

        const int cbase = lane * 8;
#pragma unroll
        for (int kk = 0; kk < 4; kk++) {
#pragma unroll 8
            for (int k2 = 0; k2 < 32; k2++) {
                const int k = kk * 32 + k2;
                const float4 w0 = *(const float4*)&Wsm[k * RR + cbase];
                const float4 w1 = *(const float4*)&Wsm[k * RR + cbase + 4];
#pragma unroll
                for (int r = 0; r < ROWS_PER_WARP; r++) {
                    const float a = __shfl_sync(FULL, o[r][kk], k2);
                    acc[r][0] = fmaf(a, w0.x, acc[r][0]);
                    acc[r][1] = fmaf(a, w0.y, acc[r][1]);
                    acc[r][2] = fmaf(a, w0.z, acc[r][2]);
                    acc[r][3] = fmaf(a, w0.w, acc[r][3]);
                    acc[r][4] = fmaf(a, w1.x, acc[r][4]);
                    acc[r][5] = fmaf(a, w1.y, acc[r][5]);
                    acc[r][6] = fmaf(a, w1.z, acc[r][6]);
                    acc[r][7] = fmaf(a, w1.w, acc[r][7]);
                }
            }
        }

        // ---- hand off to row-per-lane layout via smem ----
#pragma unroll
        for (int r = 0; r < ROWS_PER_WARP; r++) {
            *(float4*)&myj[r * JPAD + cbase]     = make_float4(acc[r][0], acc[r][1], acc[r][2], acc[r][3]);
            *(float4*)&myj[r * JPAD + cbase + 4] = make_float4(acc[r][4], acc[r][5], acc[r][6], acc[r][7]);
        }
        __syncwarp();

        // ---- LU: 2 matrices per pass (lanes 0-15 and 16-31) ----
        const int half = lane >> 4;
        const int l16  = lane & 15;
#pragma unroll
        for (int pass = 0; pass < ROWS_PER_WARP / 2; pass++) {
            const int mrow = pass * 2 + half;        // which of the warp's 4 rows
            float rr[16];
#pragma unroll
            for (int c = 0; c < 16; c++) {
                rr[c] = myj[mrow * JPAD + l16 * 16 + c]
                      + bsm[l16 * 16 + c]
                      + ((c == l16) ? 1.0f : 0.0f);   // I + j
            }
            float s, la;
            lu16x2(rr, lane, s, la);
            const int gr = rowbase + mrow;
            if (l16 == 0 && gr < nrows) {
                out_sign[gr] = s;
                out_log[gr]  = la;
            }
        }
        __syncwarp();
    }
}

extern "C" void kernel_launch(void* const* d_in, const int* in_sizes, int n_in,
                              void* d_out, int out_size) {
    const float* occ = (const float*)d_in[0];
    const float* W   = (const float*)d_in[1];
    const float* b   = (const float*)d_in[2];
    float* out = (float*)d_out;

    const int nrows = in_sizes[0] / NE;       // 262144
    float* out_sign = out;
    float* out_log  = out + nrows;            // assumed layout [sign | logabs]

    const size_t smem_bytes = SMEM_FLOATS * sizeof(float);
    static bool attr_set = false;
    if (!attr_set) {
        cudaFuncSetAttribute(jastrow_kernel,
                             cudaFuncAttributeMaxDynamicSharedMemorySize,
                             (int)smem_bytes);
        attr_set = true;
    }

    const int grid = (nrows + ROWS_PER_CTA - 1) / ROWS_PER_CTA;  // 2048
    jastrow_kernel<<<grid, THREADS, smem_bytes>>>(occ, W, b, out_sign, out_log, nrows);
}

// round 6
// speedup vs baseline: 2.6112x; 2.6112x over previous
#include <cuda_runtime.h>
#include <cuda_bf16.h>
#include <math.h>
#include <stdint.h>

// JastrowUpdate: j = occ @ W + b (B x 256), slogdet(I + j.reshape(16,16))
// out = [sign(B) | logabs(B)]
// GEMM via mma.sync m16n8k16 bf16, 3-way limb split (6 products) => fp32 accuracy.
// (Resubmission of R5 — previous round hit a container/infra failure, kernel never ran.)

#define NE      128
#define RR      256
#define MTILE   128
#define THREADS 512        // 16 warps
#define JPAD    264        // j row pitch in floats
#define LDB     272        // operand row pitch in BYTES (136 bf16)
#define ASPLIT  34816      // 128*272
#define BHALF   34816      // 128*272 (one N-half of one split)

// smem map (bytes)
#define SM_A0   0
#define SM_A1   34816
#define SM_A2   69632
#define SM_B0   104448
#define SM_B1   139264
#define SM_B2   174080
#define SM_BSM  208896     // 256 f32
#define SMEM_TOTAL (208896 + 1024 + 64)
#define SM_J    0          // phase 2: j[128][264] f32 = 135168 (reuses operands)

// precomputed W^T limbs, padded layout [n:256][k:136] bf16 (bytes)
__device__ __align__(16) unsigned char g_W0[256 * LDB];
__device__ __align__(16) unsigned char g_W1[256 * LDB];
__device__ __align__(16) unsigned char g_W2[256 * LDB];

__global__ void wconv_kernel(const float* __restrict__ W) {
    int idx = blockIdx.x * blockDim.x + threadIdx.x;   // 0..32767
    int n = idx >> 7, k = idx & 127;
    float x = W[k * RR + n];                            // Wt[n][k] = W[k][n]
    __nv_bfloat16 h0 = __float2bfloat16(x);
    float r1 = x - __bfloat162float(h0);
    __nv_bfloat16 h1 = __float2bfloat16(r1);
    float r2 = r1 - __bfloat162float(h1);
    __nv_bfloat16 h2 = __float2bfloat16(r2);
    const uint32_t o = (uint32_t)n * LDB + (uint32_t)k * 2;
    *(__nv_bfloat16*)(g_W0 + o) = h0;
    *(__nv_bfloat16*)(g_W1 + o) = h1;
    *(__nv_bfloat16*)(g_W2 + o) = h2;
}

__device__ __forceinline__ uint32_t smem_u32(const void* p) {
    uint32_t a;
    asm("{ .reg .u64 t; cvta.to.shared.u64 t, %1; cvt.u32.u64 %0, t; }" : "=r"(a) : "l"(p));
    return a;
}
__device__ __forceinline__ void ldsm4(uint32_t& r0, uint32_t& r1, uint32_t& r2, uint32_t& r3,
                                      uint32_t addr) {
    asm volatile("ldmatrix.sync.aligned.m8n8.x4.shared.b16 {%0,%1,%2,%3}, [%4];"
                 : "=r"(r0), "=r"(r1), "=r"(r2), "=r"(r3) : "r"(addr));
}
__device__ __forceinline__ void mma16816(float c[4], uint32_t a0, uint32_t a1,
                                         uint32_t a2, uint32_t a3,
                                         uint32_t b0, uint32_t b1) {
    asm volatile(
        "mma.sync.aligned.m16n8k16.row.col.f32.bf16.bf16.f32 "
        "{%0,%1,%2,%3}, {%4,%5,%6,%7}, {%8,%9}, {%0,%1,%2,%3};"
        : "+f"(c[0]), "+f"(c[1]), "+f"(c[2]), "+f"(c[3])
        : "r"(a0), "r"(a1), "r"(a2), "r"(a3), "r"(b0), "r"(b1));
}

// warp LU: 2 matrices per call (lanes 0-15 / 16-31). Validated R2.
__device__ __forceinline__ void lu16x2(float r[16], int lane,
                                       float& sign_out, float& logabs_out) {
    const unsigned FULL = 0xFFFFFFFFu;
    const int half = lane >> 4;
    const int l16  = lane & 15;
    const int base = half << 4;

    int   cur_pos = l16;
    float sign = 1.0f, logabs = 0.0f;

#pragma unroll
    for (int k = 0; k < 16; k++) {
        float cand = (cur_pos >= k) ? fabsf(r[k]) : -1.0f;
        int   idx  = l16;
#pragma unroll
        for (int d = 1; d < 16; d <<= 1) {
            float v2 = __shfl_xor_sync(FULL, cand, d);
            int   i2 = __shfl_xor_sync(FULL, idx,  d);
            if (v2 > cand || (v2 == cand && i2 < idx)) { cand = v2; idx = i2; }
        }
        const int psrc  = base + idx;
        const float piv = __shfl_sync(FULL, r[k], psrc);
        const int pos_p = __shfl_sync(FULL, cur_pos, psrc);

        if (pos_p != k) sign = -sign;
        if (cur_pos == k) cur_pos = pos_p;
        if (l16 == idx)  cur_pos = k;

        sign  *= (piv > 0.0f) ? 1.0f : ((piv < 0.0f) ? -1.0f : 0.0f);
        logabs += logf(fabsf(piv));

        const float m   = r[k] / piv;
        const bool  act = (cur_pos > k);
#pragma unroll
        for (int j = k + 1; j < 16; j++) {
            float prj = __shfl_sync(FULL, r[j], psrc);
            if (act) r[j] = fmaf(-m, prj, r[j]);
        }
    }
    sign_out = sign; logabs_out = logabs;
}

__global__ __launch_bounds__(THREADS, 1)
void jastrow_mma_kernel(const float* __restrict__ occ,
                        const float* __restrict__ b,
                        float* __restrict__ out_sign,
                        float* __restrict__ out_log,
                        int nrows) {
    extern __shared__ char smem[];
    const uint32_t sb = smem_u32(smem);
    const int tid  = threadIdx.x;
    const int lane = tid & 31;
    const int wid  = tid >> 5;
    const int tile_base = blockIdx.x * MTILE;

    // ---- stage B limbs for N-half `pass` (rows pass*128 .. +128) ----
    auto stageB = [&](int pass) {
        const int off = pass * BHALF;
        const int4* __restrict__ s0 = (const int4*)(g_W0 + off);
        const int4* __restrict__ s1 = (const int4*)(g_W1 + off);
        const int4* __restrict__ s2 = (const int4*)(g_W2 + off);
        int4* d0 = (int4*)(smem + SM_B0);
        int4* d1 = (int4*)(smem + SM_B1);
        int4* d2 = (int4*)(smem + SM_B2);
#pragma unroll
        for (int i = 0; i < 5; i++) {
            const int idx = tid + i * THREADS;
            if (idx < BHALF / 16) { d0[idx] = s0[idx]; d1[idx] = s1[idx]; d2[idx] = s2[idx]; }
        }
    };

    stageB(0);

    // ---- stage A: occ tile fp32 -> 3 bf16 limbs, padded K-major ----
    {
#pragma unroll
        for (int i = 0; i < 4096 / THREADS; i++) {
            const int e4 = tid + i * THREADS;
            const int m  = e4 >> 5;
            const int k4 = (e4 & 31) << 2;
            const float4 v = *(const float4*)&occ[(size_t)(tile_base + m) * NE + k4];
            float x[4] = {v.x, v.y, v.z, v.w};
            uint32_t p0[2], p1[2], p2[2];
            unsigned short s0[4], s1[4], s2[4];
#pragma unroll
            for (int q = 0; q < 4; q++) {
                __nv_bfloat16 h0 = __float2bfloat16(x[q]);
                float r1 = x[q] - __bfloat162float(h0);
                __nv_bfloat16 h1 = __float2bfloat16(r1);
                float r2 = r1 - __bfloat162float(h1);
                __nv_bfloat16 h2 = __float2bfloat16(r2);
                s0[q] = __bfloat16_as_ushort(h0);
                s1[q] = __bfloat16_as_ushort(h1);
                s2[q] = __bfloat16_as_ushort(h2);
            }
            p0[0] = ((uint32_t)s0[1] << 16) | s0[0]; p0[1] = ((uint32_t)s0[3] << 16) | s0[2];
            p1[0] = ((uint32_t)s1[1] << 16) | s1[0]; p1[1] = ((uint32_t)s1[3] << 16) | s1[2];
            p2[0] = ((uint32_t)s2[1] << 16) | s2[0]; p2[1] = ((uint32_t)s2[3] << 16) | s2[2];
            const uint32_t o = (uint32_t)m * LDB + (uint32_t)k4 * 2;
            *(uint2*)(smem + SM_A0 + o) = make_uint2(p0[0], p0[1]);
            *(uint2*)(smem + SM_A1 + o) = make_uint2(p1[0], p1[1]);
            *(uint2*)(smem + SM_A2 + o) = make_uint2(p2[0], p2[1]);
        }
        if (tid < RR) *(float*)(smem + SM_BSM + tid * 4) = b[tid];
    }
    __syncthreads();

    // ---- GEMM: warp tile 32(M) x 32(N per pass), K=128, 6 limb products ----
    const int mrow0 = (wid >> 2) * 32;
    const int ncl   = (wid & 3) * 32;          // column base within the current N-half

    float c[2][8][4];
#pragma unroll
    for (int mt = 0; mt < 2; mt++)
#pragma unroll
        for (int nt = 0; nt < 8; nt++)
#pragma unroll
            for (int q = 0; q < 4; q++) c[mt][nt][q] = 0.0f;

    const uint32_t lrow  = (uint32_t)(lane & 15);
    const uint32_t khalf = (uint32_t)(lane >> 4) * 16u;
    const uint32_t aoff  = (uint32_t)(mrow0 + (int)lrow) * LDB + khalf;
    const uint32_t boff  = (uint32_t)(ncl + (int)lrow) * LDB + khalf;

    const uint32_t abase[3] = { sb + SM_A0 + aoff, sb + SM_A1 + aoff, sb + SM_A2 + aoff };
    const uint32_t bbase[3] = { sb + SM_B0 + boff, sb + SM_B1 + boff, sb + SM_B2 + boff };
    // limb products, smallest first: A2B0, A0B2, A1B1, A1B0, A0B1, A0B0
    const int PA[6] = {2, 0, 1, 1, 0, 0};
    const int PB[6] = {0, 2, 1, 0, 1, 0};

#pragma unroll
    for (int pass = 0; pass < 2; pass++) {
        if (pass == 1) { __syncthreads(); stageB(1); __syncthreads(); }
#pragma unroll
        for (int prod = 0; prod < 6; prod++) {
            const uint32_t ab = abase[PA[prod]];
            const uint32_t bb = bbase[PB[prod]];
#pragma unroll
            for (int kt = 0; kt < 8; kt++) {
                const uint32_t kb = (uint32_t)kt * 32u;
                uint32_t a[2][4];
#pragma unroll
                for (int mt = 0; mt < 2; mt++)
                    ldsm4(a[mt][0], a[mt][1], a[mt][2], a[mt][3],
                          ab + (uint32_t)mt * (16u * LDB) + kb);
                uint32_t bf[4][2];
#pragma unroll
                for (int nt2 = 0; nt2 < 2; nt2++) {
                    uint32_t r0, r1, r2, r3;
                    ldsm4(r0, r1, r2, r3, bb + (uint32_t)nt2 * (16u * LDB) + kb);
                    bf[nt2 * 2 + 0][0] = r0; bf[nt2 * 2 + 0][1] = r2;
                    bf[nt2 * 2 + 1][0] = r1; bf[nt2 * 2 + 1][1] = r3;
                }
#pragma unroll
                for (int mt = 0; mt < 2; mt++)
#pragma unroll
                    for (int nt = 0; nt < 4; nt++)
                        mma16816(c[mt][pass * 4 + nt], a[mt][0], a[mt][1], a[mt][2], a[mt][3],
                                 bf[nt][0], bf[nt][1]);
            }
        }
    }

    // ---- write accumulators to j[128][JPAD] (reuses operand smem) ----
    __syncthreads();
    {
        float* jb = (float*)(smem + SM_J);
        const int qr = lane >> 2;           // 0..7
        const int qc = (lane & 3) * 2;      // 0,2,4,6
#pragma unroll
        for (int mt = 0; mt < 2; mt++) {
            const int r0 = mrow0 + mt * 16 + qr;
#pragma unroll
            for (int pass = 0; pass < 2; pass++)
#pragma unroll
                for (int nt = 0; nt < 4; nt++) {
                    const int cc = pass * 128 + ncl + nt * 8 + qc;
                    *(float2*)&jb[(size_t)r0 * JPAD + cc] =
                        make_float2(c[mt][pass * 4 + nt][0], c[mt][pass * 4 + nt][1]);
                    *(float2*)&jb[(size_t)(r0 + 8) * JPAD + cc] =
                        make_float2(c[mt][pass * 4 + nt][2], c[mt][pass * 4 + nt][3]);
                }
        }
    }
    __syncthreads();

    // ---- LU: 16 warps x 4 passes x 2 matrices = 128 samples ----
    const float* jb  = (const float*)(smem + SM_J);
    const float* bsm = (const float*)(smem + SM_BSM);
    const int half = lane >> 4;
    const int l16  = lane & 15;
#pragma unroll
    for (int pass = 0; pass < 4; pass++) {
        const int s_idx = wid * 8 + pass * 2 + half;
        const float* row = jb + (size_t)s_idx * JPAD + l16 * 16;
        float rr[16];
#pragma unroll
        for (int q = 0; q < 4; q++) {
            const float4 v  = *(const float4*)(row + q * 4);
            const float4 bv = *(const float4*)(bsm + l16 * 16 + q * 4);
            rr[q * 4 + 0] = v.x + bv.x;
            rr[q * 4 + 1] = v.y + bv.y;
            rr[q * 4 + 2] = v.z + bv.z;
            rr[q * 4 + 3] = v.w + bv.w;
        }
        rr[l16] += 1.0f;                      // I + j
        float sg, la;
        lu16x2(rr, lane, sg, la);
        const int gr = tile_base + s_idx;
        if (l16 == 0 && gr < nrows) {
            out_sign[gr] = sg;
            out_log[gr]  = la;
        }
    }
}

extern "C" void kernel_launch(void* const* d_in, const int* in_sizes, int n_in,
                              void* d_out, int out_size) {
    const float* occ = (const float*)d_in[0];
    const float* W   = (const float*)d_in[1];
    const float* b   = (const float*)d_in[2];
    float* out = (float*)d_out;

    const int nrows = in_sizes[0] / NE;
    float* out_sign = out;
    float* out_log  = out + nrows;

    static bool attr_set = false;
    if (!attr_set) {
        cudaFuncSetAttribute(jastrow_mma_kernel,
                             cudaFuncAttributeMaxDynamicSharedMemorySize, SMEM_TOTAL);
        attr_set = true;
    }

    wconv_kernel<<<128, 256>>>(W);
    const int grid = (nrows + MTILE - 1) / MTILE;
    jastrow_mma_kernel<<<grid, THREADS, SMEM_TOTAL>>>(occ, b, out_sign, out_log, nrows);
}